// round 5
// baseline (speedup 1.0000x reference)
#include <cuda_runtime.h>
#include <cuda_bf16.h>

// Problem constants (HawkesIntensityFunction: B=2, N=4096, D=256)
#define BATCH 2
#define NLEN  4096
#define DM    256
#define LOG2E 1.4426950408889634f

__device__ __forceinline__ float ex2_approx(float x) {
    float r; asm("ex2.approx.f32 %0, %1;" : "=f"(r) : "f"(x)); return r;
}
__device__ __forceinline__ float sqrt_approx(float x) {
    float r; asm("sqrt.approx.f32 %0, %1;" : "=f"(r) : "f"(x)); return r;
}

// Packed per-event data: (loc.x, loc.y, -beta*log2e*t, 0) -> one LDG.128 per pair
__device__ float4 g_packed[BATCH * NLEN];

// ---------------------------------------------------------------------------
// Kernel 1: base intensity + packing.
// One warp per row (8192 rows). Writes out[row] = mu + exp(dot+b) + alpha*(i+1)
// (the alpha*(i+1) term is the closed form of the j<=i masked entries, which
// contribute exp(0)*exp(0)=1 each since the triu mask is applied BEFORE exp).
// ---------------------------------------------------------------------------
__global__ __launch_bounds__(256)
void hawkes_setup_kernel(const float* __restrict__ z,
                         const float* __restrict__ t,
                         const float* __restrict__ loc,
                         const float* __restrict__ w,
                         const float* __restrict__ bias,
                         const float* __restrict__ mu,
                         const float* __restrict__ alpha,
                         const float* __restrict__ beta,
                         float* __restrict__ out)
{
    const int lane = threadIdx.x & 31;
    const int g    = blockIdx.x * 8 + (threadIdx.x >> 5);  // row id 0..8191
    const int i    = g & (NLEN - 1);

    const float4* wr = (const float4*)w;
    const float4  w0 = __ldg(wr + lane * 2 + 0);
    const float4  w1 = __ldg(wr + lane * 2 + 1);

    const float4* zr = (const float4*)(z + (size_t)g * DM);
    const float4  a0 = __ldg(zr + lane * 2 + 0);
    const float4  a1 = __ldg(zr + lane * 2 + 1);

    float dotp;
    dotp = a0.x * w0.x;
    dotp = fmaf(a0.y, w0.y, dotp);
    dotp = fmaf(a0.z, w0.z, dotp);
    dotp = fmaf(a0.w, w0.w, dotp);
    dotp = fmaf(a1.x, w1.x, dotp);
    dotp = fmaf(a1.y, w1.y, dotp);
    dotp = fmaf(a1.z, w1.z, dotp);
    dotp = fmaf(a1.w, w1.w, dotp);

    #pragma unroll
    for (int off = 16; off > 0; off >>= 1)
        dotp += __shfl_xor_sync(0xffffffffu, dotp, off);

    if (lane == 0) {
        const float muv = __ldg(mu);
        const float av  = __ldg(alpha);
        const float bv  = __ldg(bias);
        const float nb2 = -__ldg(beta) * LOG2E;

        const float base = ex2_approx((dotp + bv) * LOG2E);
        out[g] = muv + base + av * (float)(i + 1);

        const float2 lv = ((const float2*)loc)[g];
        g_packed[g] = make_float4(lv.x, lv.y, nb2 * __ldg(t + g), 0.0f);
    }
}

// ---------------------------------------------------------------------------
// Kernel 2: pair excitation. 8192 warps.
// Task = (b, r): rows r and NLEN-1-r  (exactly N-1 pairs per task -> balanced).
// Each task is split across 2 phase-warps (j stride 64, offset 32*phase);
// partial sums combined with atomicAdd into out (2 atomics per output elem).
// sum_{j>i} exp(-beta*dt - gamma*dist) with one fused EX2 per pair.
// ---------------------------------------------------------------------------
__global__ __launch_bounds__(256)
void hawkes_pairs_kernel(const float* __restrict__ alpha,
                         const float* __restrict__ gamma,
                         float* __restrict__ out)
{
    const int lane  = threadIdx.x & 31;
    const int gwarp = blockIdx.x * 8 + (threadIdx.x >> 5);  // 0..8191
    const int task  = gwarp >> 1;                           // 0..4095
    const int phase = gwarp & 1;
    const int b     = task >> 11;                           // / 2048
    const int r     = task & 2047;

    const float av  = __ldg(alpha);
    const float ng2 = -__ldg(gamma) * LOG2E;

    const float4* pk = g_packed + b * NLEN;

    int rows[2];
    rows[0] = r;
    rows[1] = NLEN - 1 - r;

    #pragma unroll
    for (int rr = 0; rr < 2; rr++) {
        const int i = rows[rr];
        const float4 pi = pk[i];

        float acc0 = 0.0f, acc1 = 0.0f;
        int j = i + 1 + lane + 32 * phase;

        // main loop: two independent bodies, both unconditionally in range
        for (; j < NLEN - 96; j += 128) {
            const float4 pja = __ldg(pk + j);
            const float4 pjb = __ldg(pk + j + 64);

            const float dxa = pi.x - pja.x;
            const float dya = pi.y - pja.y;
            const float sqa = fmaf(dxa, dxa, dya * dya);
            acc0 += ex2_approx(fmaf(ng2, sqrt_approx(sqa), pi.z - pja.z));

            const float dxb = pi.x - pjb.x;
            const float dyb = pi.y - pjb.y;
            const float sqb = fmaf(dxb, dxb, dyb * dyb);
            acc1 += ex2_approx(fmaf(ng2, sqrt_approx(sqb), pi.z - pjb.z));
        }
        for (; j < NLEN; j += 64) {
            const float4 pj = __ldg(pk + j);
            const float dx = pi.x - pj.x;
            const float dy = pi.y - pj.y;
            const float sq = fmaf(dx, dx, dy * dy);
            acc0 += ex2_approx(fmaf(ng2, sqrt_approx(sq), pi.z - pj.z));
        }

        float acc = acc0 + acc1;
        #pragma unroll
        for (int off = 16; off > 0; off >>= 1)
            acc += __shfl_xor_sync(0xffffffffu, acc, off);

        if (lane == 0)
            atomicAdd(out + b * NLEN + i, av * acc);
    }
}

extern "C" void kernel_launch(void* const* d_in, const int* in_sizes, int n_in,
                              void* d_out, int out_size)
{
    const float* z     = (const float*)d_in[0];
    const float* t     = (const float*)d_in[1];
    const float* loc   = (const float*)d_in[2];
    const float* w     = (const float*)d_in[3];
    const float* bias  = (const float*)d_in[4];
    const float* mu    = (const float*)d_in[5];
    const float* alpha = (const float*)d_in[6];
    const float* beta  = (const float*)d_in[7];
    const float* gamma = (const float*)d_in[8];
    float* out = (float*)d_out;

    // Kernel 1: 8192 rows, 1 warp/row -> 1024 blocks of 256
    hawkes_setup_kernel<<<1024, 256>>>(z, t, loc, w, bias, mu, alpha, beta, out);
    // Kernel 2: 8192 warps (4096 tasks x 2 phases) -> 1024 blocks of 256
    hawkes_pairs_kernel<<<1024, 256>>>(alpha, gamma, out);
}

// round 6
// speedup vs baseline: 1.0695x; 1.0695x over previous
#include <cuda_runtime.h>
#include <cuda_bf16.h>

// Problem constants (HawkesIntensityFunction: B=2, N=4096, D=256)
#define BATCH 2
#define NLEN  4096
#define DM    256
#define LOG2E 1.4426950408889634f

__device__ __forceinline__ float ex2_approx(float x) {
    float r; asm("ex2.approx.f32 %0, %1;" : "=f"(r) : "f"(x)); return r;
}
__device__ __forceinline__ float sqrt_approx(float x) {
    float r; asm("sqrt.approx.f32 %0, %1;" : "=f"(r) : "f"(x)); return r;
}

// Packed per-event data: (x, y, u = -beta*log2e*t, E = 2^{-u})
// Pair term: 2^{u_i - u_j + ng2*d} = 2^{u_i} * E_j * ex2(ng2*d)
// -> per-pair work has NO dependence on u_i except a final per-row scale.
__device__ float4 g_packed[BATCH * NLEN];

// ---------------------------------------------------------------------------
// Kernel 1: base intensity + packing.
// One warp per row (8192 rows). Writes out[row] = mu + exp(dot+b) + alpha*(i+1)
// (alpha*(i+1) is the closed form of the j<=i masked entries, which contribute
// exp(0)*exp(0)=1 each since the triu mask is applied BEFORE exp).
// ---------------------------------------------------------------------------
__global__ __launch_bounds__(256)
void hawkes_setup_kernel(const float* __restrict__ z,
                         const float* __restrict__ t,
                         const float* __restrict__ loc,
                         const float* __restrict__ w,
                         const float* __restrict__ bias,
                         const float* __restrict__ mu,
                         const float* __restrict__ alpha,
                         const float* __restrict__ beta,
                         float* __restrict__ out)
{
    const int lane = threadIdx.x & 31;
    const int g    = blockIdx.x * 8 + (threadIdx.x >> 5);  // row id 0..8191
    const int i    = g & (NLEN - 1);

    const float4* wr = (const float4*)w;
    const float4  w0 = __ldg(wr + lane * 2 + 0);
    const float4  w1 = __ldg(wr + lane * 2 + 1);

    const float4* zr = (const float4*)(z + (size_t)g * DM);
    const float4  a0 = __ldg(zr + lane * 2 + 0);
    const float4  a1 = __ldg(zr + lane * 2 + 1);

    float dotp;
    dotp = a0.x * w0.x;
    dotp = fmaf(a0.y, w0.y, dotp);
    dotp = fmaf(a0.z, w0.z, dotp);
    dotp = fmaf(a0.w, w0.w, dotp);
    dotp = fmaf(a1.x, w1.x, dotp);
    dotp = fmaf(a1.y, w1.y, dotp);
    dotp = fmaf(a1.z, w1.z, dotp);
    dotp = fmaf(a1.w, w1.w, dotp);

    #pragma unroll
    for (int off = 16; off > 0; off >>= 1)
        dotp += __shfl_xor_sync(0xffffffffu, dotp, off);

    if (lane == 0) {
        const float muv = __ldg(mu);
        const float av  = __ldg(alpha);
        const float bv  = __ldg(bias);
        const float nb2 = -__ldg(beta) * LOG2E;

        const float base = ex2_approx((dotp + bv) * LOG2E);
        out[g] = muv + base + av * (float)(i + 1);

        const float2 lv = ((const float2*)loc)[g];
        const float  u  = nb2 * __ldg(t + g);      // u_j  (<= 0)
        g_packed[g] = make_float4(lv.x, lv.y, u, ex2_approx(-u));  // E_j = 2^{-u_j}
    }
}

// One pair body: 9 issue slots (LDG, 2 FADD, FMUL, FFMA, SQRT, FMUL, EX2, FFMA)
#define PAIR_BODY(PTR, ACC)                                          \
    {                                                                \
        const float4 pj = __ldg(PTR);                                \
        const float dx = pix - pj.x;                                 \
        const float dy = piy - pj.y;                                 \
        const float sq = fmaf(dx, dx, dy * dy);                      \
        ACC = fmaf(pj.w, ex2_approx(ng2 * sqrt_approx(sq)), ACC);    \
    }

// ---------------------------------------------------------------------------
// Kernel 2: pair excitation. 8192 warps in 2048 blocks of 128.
// Task = (b, r): rows r and NLEN-1-r  (exactly N-1 pairs per task -> balanced).
// Each task split across 2 phase-warps (j stride 64, offset 32*phase);
// partials combined via atomicAdd. Per-row scale 2^{u_i} applied at the end.
// ---------------------------------------------------------------------------
__global__ __launch_bounds__(128)
void hawkes_pairs_kernel(const float* __restrict__ alpha,
                         const float* __restrict__ gamma,
                         float* __restrict__ out)
{
    const int lane  = threadIdx.x & 31;
    const int gwarp = blockIdx.x * 4 + (threadIdx.x >> 5);  // 0..8191
    const int task  = gwarp >> 1;                           // 0..4095
    const int phase = gwarp & 1;
    const int b     = task >> 11;                           // / 2048
    const int r     = task & 2047;

    const float av  = __ldg(alpha);
    const float ng2 = -__ldg(gamma) * LOG2E;

    const float4* pk = g_packed + b * NLEN;

    int rows[2];
    rows[0] = r;
    rows[1] = NLEN - 1 - r;

    #pragma unroll
    for (int rr = 0; rr < 2; rr++) {
        const int i = rows[rr];
        const float4 pi = pk[i];
        const float pix = pi.x, piy = pi.y;

        float a0 = 0.0f, a1 = 0.0f, a2 = 0.0f, a3 = 0.0f;

        int j = i + 1 + lane + 32 * phase;
        const float4* p = pk + j;

        // unroll-4 main loop: one IADD of p per 4 pairs, compile-time offsets
        for (; j < NLEN - 224; j += 256, p += 256) {
            PAIR_BODY(p,       a0)
            PAIR_BODY(p +  64, a1)
            PAIR_BODY(p + 128, a2)
            PAIR_BODY(p + 192, a3)
        }
        for (; j < NLEN; j += 64, p += 64) {
            PAIR_BODY(p, a0)
        }

        float acc = (a0 + a1) + (a2 + a3);
        #pragma unroll
        for (int off = 16; off > 0; off >>= 1)
            acc += __shfl_xor_sync(0xffffffffu, acc, off);

        if (lane == 0) {
            const float scale = ex2_approx(pi.z);   // 2^{u_i}
            atomicAdd(out + b * NLEN + i, av * scale * acc);
        }
    }
}

extern "C" void kernel_launch(void* const* d_in, const int* in_sizes, int n_in,
                              void* d_out, int out_size)
{
    const float* z     = (const float*)d_in[0];
    const float* t     = (const float*)d_in[1];
    const float* loc   = (const float*)d_in[2];
    const float* w     = (const float*)d_in[3];
    const float* bias  = (const float*)d_in[4];
    const float* mu    = (const float*)d_in[5];
    const float* alpha = (const float*)d_in[6];
    const float* beta  = (const float*)d_in[7];
    const float* gamma = (const float*)d_in[8];
    float* out = (float*)d_out;

    // Kernel 1: 8192 rows, 1 warp/row -> 1024 blocks of 256
    hawkes_setup_kernel<<<1024, 256>>>(z, t, loc, w, bias, mu, alpha, beta, out);
    // Kernel 2: 8192 warps -> 2048 blocks of 128
    hawkes_pairs_kernel<<<2048, 128>>>(alpha, gamma, out);
}

// round 7
// speedup vs baseline: 1.1980x; 1.1201x over previous
#include <cuda_runtime.h>
#include <cuda_bf16.h>

// Problem constants (HawkesIntensityFunction: B=2, N=4096, D=256)
#define BATCH 2
#define NLEN  4096
#define DM    256
#define LOG2E 1.4426950408889634f

#define ROWS_PB 256          // rows per block (== blockDim.x)
#define TJ      128          // j-tile size (events in smem)
#define RT_CNT  (NLEN / ROWS_PB)             // 16 row tiles per batch
#define JT_CNT  (NLEN / TJ)                  // 32 j tiles per batch
#define BLOCKS_PER_BATCH 272                 // sum_{rt=0..15} (32 - 2*rt)

__device__ __forceinline__ float ex2_approx(float x) {
    float r; asm("ex2.approx.f32 %0, %1;" : "=f"(r) : "f"(x)); return r;
}
__device__ __forceinline__ float sqrt_approx(float x) {
    float r; asm("sqrt.approx.f32 %0, %1;" : "=f"(r) : "f"(x)); return r;
}

// Packed per-event: (x, y, u = -beta*log2e*t, E = 2^{-u})
// Pair term for j>i:  alpha * 2^{u_i} * E_j * ex2(ng2 * dist_ij)
__device__ float4 g_packed[BATCH * NLEN];

// ---------------------------------------------------------------------------
// Kernel 1: base intensity + packing.  One warp per row (8192 rows).
// out[row] = mu + exp(dot+b) + alpha*(i+1)   (closed form of the j<=i masked
// entries: triu mask applied BEFORE exp -> each contributes exp(0)*exp(0)=1).
// ---------------------------------------------------------------------------
__global__ __launch_bounds__(256)
void hawkes_setup_kernel(const float* __restrict__ z,
                         const float* __restrict__ t,
                         const float* __restrict__ loc,
                         const float* __restrict__ w,
                         const float* __restrict__ bias,
                         const float* __restrict__ mu,
                         const float* __restrict__ alpha,
                         const float* __restrict__ beta,
                         float* __restrict__ out)
{
    const int lane = threadIdx.x & 31;
    const int g    = blockIdx.x * 8 + (threadIdx.x >> 5);  // row id 0..8191
    const int i    = g & (NLEN - 1);

    const float4* wr = (const float4*)w;
    const float4  w0 = __ldg(wr + lane * 2 + 0);
    const float4  w1 = __ldg(wr + lane * 2 + 1);

    const float4* zr = (const float4*)(z + (size_t)g * DM);
    const float4  a0 = __ldg(zr + lane * 2 + 0);
    const float4  a1 = __ldg(zr + lane * 2 + 1);

    float dotp;
    dotp = a0.x * w0.x;
    dotp = fmaf(a0.y, w0.y, dotp);
    dotp = fmaf(a0.z, w0.z, dotp);
    dotp = fmaf(a0.w, w0.w, dotp);
    dotp = fmaf(a1.x, w1.x, dotp);
    dotp = fmaf(a1.y, w1.y, dotp);
    dotp = fmaf(a1.z, w1.z, dotp);
    dotp = fmaf(a1.w, w1.w, dotp);

    #pragma unroll
    for (int off = 16; off > 0; off >>= 1)
        dotp += __shfl_xor_sync(0xffffffffu, dotp, off);

    if (lane == 0) {
        const float muv = __ldg(mu);
        const float av  = __ldg(alpha);
        const float bv  = __ldg(bias);
        const float nb2 = -__ldg(beta) * LOG2E;

        const float base = ex2_approx((dotp + bv) * LOG2E);
        out[g] = muv + base + av * (float)(i + 1);

        const float2 lv = ((const float2*)loc)[g];
        const float  u  = nb2 * __ldg(t + g);
        g_packed[g] = make_float4(lv.x, lv.y, u, ex2_approx(-u));  // E = 2^{-u}
    }
}

// pair math from a broadcast smem event v against this thread's row (pix,piy)
#define PAIR_MATH(V, E_OUT)                                   \
    float E_OUT;                                              \
    {                                                         \
        const float dx = pix - (V).x;                         \
        const float dy = piy - (V).y;                         \
        const float sq = fmaf(dx, dx, dy * dy);               \
        E_OUT = (V).w * ex2_approx(ng2 * sqrt_approx(sq));    \
    }

// ---------------------------------------------------------------------------
// Kernel 2: pair excitation, tiled. Block = 256 threads = 256 rows.
// j-tile of 128 events broadcast from smem (LDS.128 broadcast, ~free).
// Interior tiles (all j > all i): no mask. Diagonal tiles: predicated j>i.
// Partial row sums merged with one atomicAdd per thread per block.
// ---------------------------------------------------------------------------
__global__ __launch_bounds__(256)
void hawkes_pairs_kernel(const float* __restrict__ alpha,
                         const float* __restrict__ gamma,
                         float* __restrict__ out)
{
    __shared__ float4 tile[TJ];

    // decode (b, rt, jt) from blockIdx.x; jt >= 2*rt (triangular tile set)
    int x = blockIdx.x;
    int b = 0;
    if (x >= BLOCKS_PER_BATCH) { b = 1; x -= BLOCKS_PER_BATCH; }
    int rt = 0;
    while (x >= JT_CNT - 2 * rt) { x -= JT_CNT - 2 * rt; rt++; }
    const int jt = 2 * rt + x;

    const float av  = __ldg(alpha);
    const float ng2 = -__ldg(gamma) * LOG2E;

    const float4* pk = g_packed + b * NLEN;
    const int tid     = threadIdx.x;
    const int rowbase = rt * ROWS_PB;
    const int jbase   = jt * TJ;

    if (tid < TJ) tile[tid] = __ldg(pk + jbase + tid);
    __syncthreads();

    const int i = rowbase + tid;
    const float4 pi = pk[i];
    const float pix = pi.x, piy = pi.y;

    float a0 = 0.0f, a1 = 0.0f, a2 = 0.0f, a3 = 0.0f;

    if (jbase >= rowbase + ROWS_PB) {
        // interior tile: every j > every i, no masking
        for (int jj = 0; jj < TJ; jj += 4) {
            const float4 v0 = tile[jj + 0];
            const float4 v1 = tile[jj + 1];
            const float4 v2 = tile[jj + 2];
            const float4 v3 = tile[jj + 3];
            PAIR_MATH(v0, e0) a0 += e0;
            PAIR_MATH(v1, e1) a1 += e1;
            PAIR_MATH(v2, e2) a2 += e2;
            PAIR_MATH(v3, e3) a3 += e3;
        }
    } else {
        // diagonal tile: keep only j > i, i.e. (jbase - rowbase + jj) > tid
        const int joff = jbase - rowbase;
        for (int jj = 0; jj < TJ; jj += 4) {
            const float4 v0 = tile[jj + 0];
            const float4 v1 = tile[jj + 1];
            const float4 v2 = tile[jj + 2];
            const float4 v3 = tile[jj + 3];
            PAIR_MATH(v0, e0) if (joff + jj + 0 > tid) a0 += e0;
            PAIR_MATH(v1, e1) if (joff + jj + 1 > tid) a1 += e1;
            PAIR_MATH(v2, e2) if (joff + jj + 2 > tid) a2 += e2;
            PAIR_MATH(v3, e3) if (joff + jj + 3 > tid) a3 += e3;
        }
    }

    const float acc = (a0 + a1) + (a2 + a3);
    const float scale = ex2_approx(pi.z);            // 2^{u_i}
    atomicAdd(out + b * NLEN + i, av * scale * acc);
}

extern "C" void kernel_launch(void* const* d_in, const int* in_sizes, int n_in,
                              void* d_out, int out_size)
{
    const float* z     = (const float*)d_in[0];
    const float* t     = (const float*)d_in[1];
    const float* loc   = (const float*)d_in[2];
    const float* w     = (const float*)d_in[3];
    const float* bias  = (const float*)d_in[4];
    const float* mu    = (const float*)d_in[5];
    const float* alpha = (const float*)d_in[6];
    const float* beta  = (const float*)d_in[7];
    const float* gamma = (const float*)d_in[8];
    float* out = (float*)d_out;

    // Kernel 1: 8192 rows, 1 warp/row -> 1024 blocks of 256
    hawkes_setup_kernel<<<1024, 256>>>(z, t, loc, w, bias, mu, alpha, beta, out);
    // Kernel 2: 2 * 272 triangular tiles, 256 threads each
    hawkes_pairs_kernel<<<2 * BLOCKS_PER_BATCH, 256>>>(alpha, gamma, out);
}